// round 8
// baseline (speedup 1.0000x reference)
#include <cuda_runtime.h>

// ---------------------------------------------------------------------------
// StepWiseMLPAutoEncoder — fp32, packed fma.rn.f32x2
// encoder: 128x64-tile GEMMs (512 thr, 2 blocks/SM)
// decoder: persistent kernel, flag-scan grid barrier (parallel arrivals),
//          coalesced step outputs into g_outT, final transpose
// ---------------------------------------------------------------------------

#define BATCH 64
#define SS    1024
#define TT    256
#define HH    64
#define EM    1056
#define DM    1056
#define KC    2048
#define KD1   1088
#define MROWS (BATCH*TT)
#define NBLK  132

typedef unsigned long long u64;

// scratch (device globals; padded for prefetch overshoot)
__device__ float g_xT[BATCH * TT * SS];
__device__ float g_h1[(size_t)MROWS * EM];
__device__ float g_ctrlT[TT * HH * BATCH + 1024];   // [T,H,B] k-major
__device__ float g_hdT[DM * BATCH + 1024];          // [K,B]
__device__ float g_outT[TT * SS * BATCH + 1024];    // [T,S,B]  (also = prev buffer)
__device__ float g_zero[SS * BATCH + 512];          // never written -> stays 0

// barrier state: per-block arrival flags (128B apart) + one release word
__device__ unsigned g_arrive[NBLK * 32];
__device__ unsigned g_release[32];

// ---- packed fp32x2 helpers -------------------------------------------------
__device__ __forceinline__ u64 pk2(float lo, float hi) {
    u64 r; asm("mov.b64 %0, {%1, %2};" : "=l"(r) : "f"(lo), "f"(hi)); return r;
}
__device__ __forceinline__ void fma2(u64& d, u64 a, u64 b) {
    asm("fma.rn.f32x2 %0, %1, %2, %0;" : "+l"(d) : "l"(a), "l"(b));
}
__device__ __forceinline__ void unpk2(u64 v, float& lo, float& hi) {
    asm("mov.b64 {%0, %1}, %2;" : "=f"(lo), "=f"(hi) : "l"(v));
}

// ---------------------------------------------------------------------------
// flag-scan grid barrier: parallel arrivals, block-0 warp-0 scan, 1 release.
// ph is a monotonically increasing epoch (base derived from persistent flags,
// so graph replays are deterministic).
// ---------------------------------------------------------------------------
__device__ __forceinline__ void fast_sync(int bid, unsigned ph)
{
    __syncthreads();
    if (threadIdx.x == 0) {
        __threadfence();
        *(volatile unsigned*)&g_arrive[bid * 32] = ph;
    }
    if (bid == 0) {
        if (threadIdx.x < 32) {
            bool pending = true;
            while (pending) {
                bool p = false;
#pragma unroll
                for (int i = 0; i < 5; i++) {
                    int b = threadIdx.x + i * 32;
                    if (b < NBLK &&
                        *(volatile unsigned*)&g_arrive[b * 32] < ph)
                        p = true;
                }
                pending = __any_sync(0xffffffffu, p);
            }
            if (threadIdx.x == 0) {
                __threadfence();
                *(volatile unsigned*)&g_release[0] = ph;
            }
        }
    } else {
        if (threadIdx.x == 0) {
            while (*(volatile unsigned*)&g_release[0] < ph) { }
            __threadfence();
        }
    }
    __syncthreads();
}

// ---------------------------------------------------------------------------
// x[b,s,t] -> xT[b,t,s]
// ---------------------------------------------------------------------------
__global__ void transpose_x_kernel(const float* __restrict__ x)
{
    __shared__ float tile[32][33];
    int b  = blockIdx.z;
    int t0 = blockIdx.x * 32;
    int s0 = blockIdx.y * 32;
    const float* xb  = x    + (size_t)b * SS * TT;
    float*       xTb = g_xT + (size_t)b * TT * SS;
    int tx = threadIdx.x, ty = threadIdx.y;
#pragma unroll
    for (int j = 0; j < 32; j += 8)
        tile[ty + j][tx] = xb[(s0 + ty + j) * TT + t0 + tx];
    __syncthreads();
#pragma unroll
    for (int j = 0; j < 32; j += 8)
        xTb[(t0 + ty + j) * SS + s0 + tx] = tile[tx][ty + j];
}

// ---------------------------------------------------------------------------
// final: g_outT[t,s,b] -> out[b,s,t]
// ---------------------------------------------------------------------------
__global__ void transpose_out_kernel(float* __restrict__ out)
{
    __shared__ float tile[32][33];
    int t0 = blockIdx.x * 32;
    int b0 = blockIdx.y * 32;
    int s  = blockIdx.z;
    int tx = threadIdx.x, ty = threadIdx.y;
#pragma unroll
    for (int j = 0; j < 32; j += 8)
        tile[ty + j][tx] = g_outT[(size_t)(t0 + ty + j) * SS * BATCH + s * BATCH + b0 + tx];
    __syncthreads();
#pragma unroll
    for (int j = 0; j < 32; j += 8)
        out[(size_t)(b0 + ty + j) * SS * TT + (size_t)s * TT + t0 + tx] = tile[tx][ty + j];
}

// ---------------------------------------------------------------------------
// Encoder GEMM, 128x64 tile, BK=16, 512 threads, 4m x 4n per thread, f32x2.
// ---------------------------------------------------------------------------
template<int MODE>
__global__ __launch_bounds__(512, 2) void enc_gemm_kernel(
    const float* __restrict__ Bmat, const float* __restrict__ bias)
{
    constexpr int N = (MODE == 0) ? EM : HH;
    constexpr int K = (MODE == 0) ? KC : EM;

    __shared__ float As[16][132];
    __shared__ float Bs[16][68];

    int tid  = threadIdx.x;
    int arow = tid >> 2;
    int acol = (tid & 3) * 4;
    int bk   = tid >> 5;
    int bn   = (tid & 31) * 2;
    int tn   = tid & 15;
    int tm   = tid >> 4;
    int n0   = blockIdx.x * 64;
    int r0   = blockIdx.y * 128;

    u64 acc2[4][2];
#pragma unroll
    for (int i = 0; i < 4; i++) { acc2[i][0] = 0ULL; acc2[i][1] = 0ULL; }

    int r = r0 + arow;
    const float* aprev = nullptr;
    const float* acur  = nullptr;
    if (MODE == 0) {
        int bb = r >> 8;
        int t  = r & 255;
        acur  = g_xT + ((size_t)((bb << 8) + t)) * SS;
        aprev = (t > 0) ? (acur - SS) : nullptr;
    } else {
        acur = g_h1 + (size_t)r * K;
    }

    for (int kc = 0; kc < K; kc += 16) {
        float4 av = make_float4(0.f, 0.f, 0.f, 0.f);
        int kg = kc + acol;
        if (MODE == 0) {
            if (kg < SS) {
                if (aprev) av = *(const float4*)(aprev + kg);
            } else {
                av = *(const float4*)(acur + kg - SS);
            }
        } else {
            av = *(const float4*)(acur + kg);
        }
        As[acol + 0][arow] = av.x;
        As[acol + 1][arow] = av.y;
        As[acol + 2][arow] = av.z;
        As[acol + 3][arow] = av.w;

        {
            int ng = n0 + bn;
            float2 bv = make_float2(0.f, 0.f);
            if (ng < N) bv = *(const float2*)&Bmat[(size_t)(kc + bk) * N + ng];
            Bs[bk][bn]     = bv.x;
            Bs[bk][bn + 1] = bv.y;
        }
        __syncthreads();

#pragma unroll
        for (int kk = 0; kk < 16; kk++) {
            float4 a4 = *(const float4*)&As[kk][tm * 4];
            ulonglong2 b2 = *(const ulonglong2*)&Bs[kk][tn * 4];
            u64 d0 = pk2(a4.x, a4.x);
            u64 d1 = pk2(a4.y, a4.y);
            u64 d2 = pk2(a4.z, a4.z);
            u64 d3 = pk2(a4.w, a4.w);
            fma2(acc2[0][0], d0, b2.x); fma2(acc2[0][1], d0, b2.y);
            fma2(acc2[1][0], d1, b2.x); fma2(acc2[1][1], d1, b2.y);
            fma2(acc2[2][0], d2, b2.x); fma2(acc2[2][1], d2, b2.y);
            fma2(acc2[3][0], d3, b2.x); fma2(acc2[3][1], d3, b2.y);
        }
        __syncthreads();
    }

#pragma unroll
    for (int i = 0; i < 4; i++) {
        float c[4];
        unpk2(acc2[i][0], c[0], c[1]);
        unpk2(acc2[i][1], c[2], c[3]);
        int rr = r0 + tm * 4 + i;
#pragma unroll
        for (int j = 0; j < 4; j++) {
            int ng = n0 + tn * 4 + j;
            if (ng < N) {
                float v = c[j] + bias[ng];
                if (MODE == 0) {
                    g_h1[(size_t)rr * EM + ng] = fmaxf(v, 0.f);
                } else {
                    int bb = rr >> 8;
                    int tt = rr & 255;
                    g_ctrlT[(tt * HH + ng) * BATCH + bb] = v;
                }
            }
        }
    }
}

// ---------------------------------------------------------------------------
// Persistent decoder.
// 132 blocks x 512 thr. Block = (n-tile nt = bid>>1, batch-half mh = bid&1):
// 16 n-cols x 32 m-rows. 16 warps = 16 k-split groups (1 warp each).
// ---------------------------------------------------------------------------
#define DEC_SMEM ((KD1*16 + DM*16 + 16*16*32) * 4)

__device__ __forceinline__ void dec_seg(
    u64 acc[8], const float* __restrict__ src, const float* __restrict__ Ws,
    int k0, int nk, int moff)
{
    const float* s = src + moff;
    const ulonglong2* wp = (const ulonglong2*)(Ws + k0 * 16);
    float av[4];
#pragma unroll
    for (int kk = 0; kk < 4; kk++) av[kk] = s[64 * kk];

    for (int i = 0; i < nk; i += 4) {
        s += 256;
        float nv[4];
#pragma unroll
        for (int kk = 0; kk < 4; kk++) nv[kk] = s[64 * kk];  // prefetch (padded)
#pragma unroll
        for (int kk = 0; kk < 4; kk++) {
            u64 ad = pk2(av[kk], av[kk]);
            ulonglong2 w0 = wp[0], w1 = wp[1], w2 = wp[2], w3 = wp[3];
            wp += 4;
            fma2(acc[0], ad, w0.x); fma2(acc[1], ad, w0.y);
            fma2(acc[2], ad, w1.x); fma2(acc[3], ad, w1.y);
            fma2(acc[4], ad, w2.x); fma2(acc[5], ad, w2.y);
            fma2(acc[6], ad, w3.x); fma2(acc[7], ad, w3.y);
        }
#pragma unroll
        for (int kk = 0; kk < 4; kk++) av[kk] = nv[kk];
    }
}

__global__ __launch_bounds__(512) void dec_persistent_kernel(
    const float* __restrict__ Wd1, const float* __restrict__ bd1,
    const float* __restrict__ Wd2, const float* __restrict__ bd2)
{
    extern __shared__ float sm[];
    float* Ws1 = sm;                        // [KD1][16]
    float* Ws2 = sm + KD1 * 16;             // [DM][16]
    float* red = sm + (KD1 + DM) * 16;      // [16g][16n][32m]

    int tid = threadIdx.x;
    int bid = blockIdx.x;
    int nt  = bid >> 1;          // n-tile 0..65
    int mh  = bid & 1;           // batch half
    int n0  = nt * 16;

    // replay-safe epoch base: my own flag's current value
    unsigned ph = *(volatile unsigned*)&g_arrive[bid * 32] + 1u;

    // one-time: cache weight slices k-row-major [k][16]
    for (int i = tid; i < 16 * KD1; i += 512) {
        int k = i >> 4, n = i & 15;
        Ws1[i] = Wd1[(size_t)k * DM + n0 + n];
    }
    if (nt < 64) {
        for (int i = tid; i < 16 * DM; i += 512) {
            int k = i >> 4, n = i & 15;
            Ws2[i] = Wd2[(size_t)k * SS + n0 + n];
        }
    }

    int g    = tid >> 5;
    int lane = tid & 31;
    int moff = mh * 32 + lane;
    int en   = tid >> 5;
    int em   = tid & 31;

    float bv1 = bd1[n0 + en];
    float bv2 = (nt < 64) ? bd2[n0 + en] : 0.f;

    int kb1 = g * 68;                                    // 16 x 68 = 1088
    int kb2 = (g < 8) ? g * 68 : 544 + (g - 8) * 64;     // 8x68 + 8x64 = 1056
    int nk2 = (g < 8) ? 68 : 64;

    for (int t = 0; t < TT; t++) {
        const float* prevT = (t == 0) ? g_zero
                                      : g_outT + (size_t)(t - 1) * SS * BATCH;
        const float* ctrl_base = g_ctrlT + t * HH * BATCH;

        // ---- layer 1: g_hdT = relu([ctrl_t | prev] @ Wd1 + bd1), K=1088
        {
            u64 acc[8] = {};
            if (g == 0) {
                dec_seg(acc, ctrl_base, Ws1, 0, 64, moff);
                dec_seg(acc, prevT, Ws1, 64, 4, moff);
            } else {
                dec_seg(acc, prevT + (kb1 - HH) * 64, Ws1, kb1, 68, moff);
            }
#pragma unroll
            for (int p = 0; p < 8; p++) {
                float lo, hi; unpk2(acc[p], lo, hi);
                red[(g * 16 + 2 * p) * 32 + lane]     = lo;
                red[(g * 16 + 2 * p + 1) * 32 + lane] = hi;
            }
            __syncthreads();

            float v = bv1;
#pragma unroll
            for (int gg = 0; gg < 16; gg++)
                v += red[(gg * 16 + en) * 32 + em];
            g_hdT[(n0 + en) * 64 + mh * 32 + em] = fmaxf(v, 0.f);
        }
        fast_sync(bid, ph); ph++;

        // ---- layer 2: out_t = g_hd @ Wd2 + bd2, K=1056
        if (nt < 64) {
            u64 acc[8] = {};
            dec_seg(acc, g_hdT + kb2 * 64, Ws2, kb2, nk2, moff);
#pragma unroll
            for (int p = 0; p < 8; p++) {
                float lo, hi; unpk2(acc[p], lo, hi);
                red[(g * 16 + 2 * p) * 32 + lane]     = lo;
                red[(g * 16 + 2 * p + 1) * 32 + lane] = hi;
            }
            __syncthreads();

            float v = bv2;
#pragma unroll
            for (int gg = 0; gg < 16; gg++)
                v += red[(gg * 16 + en) * 32 + em];
            int s = n0 + en;
            g_outT[(size_t)t * SS * BATCH + s * BATCH + mh * 32 + em] = v;
        }
        fast_sync(bid, ph); ph++;
    }
}

// ---------------------------------------------------------------------------
extern "C" void kernel_launch(void* const* d_in, const int* in_sizes, int n_in,
                              void* d_out, int out_size)
{
    const float* x   = (const float*)d_in[0];
    const float* We1 = (const float*)d_in[1];
    const float* be1 = (const float*)d_in[2];
    const float* We2 = (const float*)d_in[3];
    const float* be2 = (const float*)d_in[4];
    const float* Wd1 = (const float*)d_in[5];
    const float* bd1 = (const float*)d_in[6];
    const float* Wd2 = (const float*)d_in[7];
    const float* bd2 = (const float*)d_in[8];
    float* out = (float*)d_out;

    cudaFuncSetAttribute(dec_persistent_kernel,
                         cudaFuncAttributeMaxDynamicSharedMemorySize, DEC_SMEM);

    // encoder (parallel)
    transpose_x_kernel<<<dim3(TT / 32, SS / 32, BATCH), dim3(32, 8)>>>(x);
    enc_gemm_kernel<0><<<dim3((EM + 63) / 64, MROWS / 128), 512>>>(We1, be1);
    enc_gemm_kernel<1><<<dim3(1, MROWS / 128), 512>>>(We2, be2);

    // decoder: persistent kernel over all 256 steps
    dec_persistent_kernel<<<NBLK, 512, DEC_SMEM>>>(Wd1, bd1, Wd2, bd2);

    // final layout fix: g_outT[t,s,b] -> out[b,s,t]
    transpose_out_kernel<<<dim3(TT / 32, BATCH / 32, SS), dim3(32, 8)>>>(out);
}

// round 9
// speedup vs baseline: 1.1050x; 1.1050x over previous
#include <cuda_runtime.h>

// ---------------------------------------------------------------------------
// StepWiseMLPAutoEncoder — fp32, packed fma.rn.f32x2
// decoder: persistent kernel, NO grid barriers — fine-grained per-tile
//          release/acquire dataflow flags between layer1 and layer2.
// ---------------------------------------------------------------------------

#define BATCH 64
#define SS    1024
#define TT    256
#define HH    64
#define EM    1056
#define DM    1056
#define KC    2048
#define KD1   1088
#define MROWS (BATCH*TT)
#define NBLK  132

typedef unsigned long long u64;

// scratch (device globals; padded for prefetch overshoot)
__device__ float g_xT[BATCH * TT * SS];
__device__ float g_h1[(size_t)MROWS * EM];
__device__ float g_ctrlT[TT * HH * BATCH + 1024];   // [T,H,B] k-major
__device__ float g_hdT[DM * BATCH + 1024];          // [K,B]
__device__ float g_outT[TT * SS * BATCH + 1024];    // [T,S,B] (= prev buffer)
__device__ float g_zero[SS * BATCH + 1024];         // never written -> stays 0

// dataflow flags: one line (128B) per (tile, mh)
__device__ unsigned g_flag1[66 * 2 * 32];           // layer1 outputs (hdT tiles)
__device__ unsigned g_flag2[64 * 2 * 32];           // layer2 outputs (outT tiles)

// ---- packed fp32x2 helpers -------------------------------------------------
__device__ __forceinline__ u64 pk2(float lo, float hi) {
    u64 r; asm("mov.b64 %0, {%1, %2};" : "=l"(r) : "f"(lo), "f"(hi)); return r;
}
__device__ __forceinline__ void fma2(u64& d, u64 a, u64 b) {
    asm("fma.rn.f32x2 %0, %1, %2, %0;" : "+l"(d) : "l"(a), "l"(b));
}
__device__ __forceinline__ void unpk2(u64 v, float& lo, float& hi) {
    asm("mov.b64 {%0, %1}, %2;" : "=f"(lo), "=f"(hi) : "l"(v));
}

// ---- flag primitives --------------------------------------------------------
__device__ __forceinline__ unsigned ld_rlx(const unsigned* p) {
    unsigned v; asm volatile("ld.relaxed.gpu.u32 %0, [%1];" : "=r"(v) : "l"(p));
    return v;
}
__device__ __forceinline__ void st_rel(unsigned* p, unsigned v) {
    asm volatile("st.release.gpu.u32 [%0], %1;" :: "l"(p), "r"(v));
}
__device__ __forceinline__ void fence_acq() {
    asm volatile("fence.acq_rel.gpu;" ::: "memory");
}
// wait until flags[(p*2+mh)*32] >= target for all p in [p0,p1]
__device__ __forceinline__ void wait_tiles(const unsigned* flags, int mh,
                                           int p0, int p1, unsigned target)
{
    for (;;) {
        bool ok = true;
        for (int p = p0; p <= p1; p++)
            ok &= (ld_rlx(&flags[(p * 2 + mh) * 32]) >= target);
        if (ok) break;
    }
    fence_acq();
}

// ---------------------------------------------------------------------------
// x[b,s,t] -> xT[b,t,s]
// ---------------------------------------------------------------------------
__global__ void transpose_x_kernel(const float* __restrict__ x)
{
    __shared__ float tile[32][33];
    int b  = blockIdx.z;
    int t0 = blockIdx.x * 32;
    int s0 = blockIdx.y * 32;
    const float* xb  = x    + (size_t)b * SS * TT;
    float*       xTb = g_xT + (size_t)b * TT * SS;
    int tx = threadIdx.x, ty = threadIdx.y;
#pragma unroll
    for (int j = 0; j < 32; j += 8)
        tile[ty + j][tx] = xb[(s0 + ty + j) * TT + t0 + tx];
    __syncthreads();
#pragma unroll
    for (int j = 0; j < 32; j += 8)
        xTb[(t0 + ty + j) * SS + s0 + tx] = tile[tx][ty + j];
}

// ---------------------------------------------------------------------------
// final: g_outT[t,s,b] -> out[b,s,t]
// ---------------------------------------------------------------------------
__global__ void transpose_out_kernel(float* __restrict__ out)
{
    __shared__ float tile[32][33];
    int t0 = blockIdx.x * 32;
    int b0 = blockIdx.y * 32;
    int s  = blockIdx.z;
    int tx = threadIdx.x, ty = threadIdx.y;
#pragma unroll
    for (int j = 0; j < 32; j += 8)
        tile[ty + j][tx] = g_outT[(size_t)(t0 + ty + j) * SS * BATCH + s * BATCH + b0 + tx];
    __syncthreads();
#pragma unroll
    for (int j = 0; j < 32; j += 8)
        out[(size_t)(b0 + ty + j) * SS * TT + (size_t)s * TT + t0 + tx] = tile[tx][ty + j];
}

// ---------------------------------------------------------------------------
// Encoder GEMM, 64x64 tile, BK=16, 256 threads, 4m x 4n per thread, f32x2.
// (R4-proven configuration)
// ---------------------------------------------------------------------------
template<int MODE>
__global__ __launch_bounds__(256) void enc_gemm_kernel(
    const float* __restrict__ Bmat, const float* __restrict__ bias)
{
    constexpr int N = (MODE == 0) ? EM : HH;
    constexpr int K = (MODE == 0) ? KC : EM;

    __shared__ float As[16][64];
    __shared__ float Bs[16][64];

    int tid  = threadIdx.x;
    int arow = tid >> 2;
    int acol = (tid & 3) * 4;
    int tn   = tid & 15;
    int tm   = tid >> 4;
    int n0   = blockIdx.x * 64;
    int r0   = blockIdx.y * 64;

    u64 acc2[4][2];
#pragma unroll
    for (int i = 0; i < 4; i++) { acc2[i][0] = 0ULL; acc2[i][1] = 0ULL; }

    int r = r0 + arow;
    const float* aprev = nullptr;
    const float* acur  = nullptr;
    if (MODE == 0) {
        int bb = r >> 8;
        int t  = r & 255;
        acur  = g_xT + ((size_t)((bb << 8) + t)) * SS;
        aprev = (t > 0) ? (acur - SS) : nullptr;
    } else {
        acur = g_h1 + (size_t)r * K;
    }

    for (int kc = 0; kc < K; kc += 16) {
        float4 av = make_float4(0.f, 0.f, 0.f, 0.f);
        int kg = kc + acol;
        if (MODE == 0) {
            if (kg < SS) {
                if (aprev) av = *(const float4*)(aprev + kg);
            } else {
                av = *(const float4*)(acur + kg - SS);
            }
        } else {
            av = *(const float4*)(acur + kg);
        }
        As[acol + 0][arow] = av.x;
        As[acol + 1][arow] = av.y;
        As[acol + 2][arow] = av.z;
        As[acol + 3][arow] = av.w;

#pragma unroll
        for (int it = 0; it < 4; it++) {
            int k = (tid >> 6) + it * 4;
            int n = tid & 63;
            int ng = n0 + n;
            float v = 0.f;
            if (ng < N) v = Bmat[(size_t)(kc + k) * N + ng];
            Bs[k][n] = v;
        }
        __syncthreads();

#pragma unroll
        for (int kk = 0; kk < 16; kk++) {
            float4 a4 = *(const float4*)&As[kk][tm * 4];
            ulonglong2 b2 = *(const ulonglong2*)&Bs[kk][tn * 4];
            u64 d0 = pk2(a4.x, a4.x);
            u64 d1 = pk2(a4.y, a4.y);
            u64 d2 = pk2(a4.z, a4.z);
            u64 d3 = pk2(a4.w, a4.w);
            fma2(acc2[0][0], d0, b2.x); fma2(acc2[0][1], d0, b2.y);
            fma2(acc2[1][0], d1, b2.x); fma2(acc2[1][1], d1, b2.y);
            fma2(acc2[2][0], d2, b2.x); fma2(acc2[2][1], d2, b2.y);
            fma2(acc2[3][0], d3, b2.x); fma2(acc2[3][1], d3, b2.y);
        }
        __syncthreads();
    }

#pragma unroll
    for (int i = 0; i < 4; i++) {
        float c[4];
        unpk2(acc2[i][0], c[0], c[1]);
        unpk2(acc2[i][1], c[2], c[3]);
        int rr = r0 + tm * 4 + i;
#pragma unroll
        for (int j = 0; j < 4; j++) {
            int ng = n0 + tn * 4 + j;
            if (ng < N) {
                float v = c[j] + bias[ng];
                if (MODE == 0) {
                    g_h1[(size_t)rr * EM + ng] = fmaxf(v, 0.f);
                } else {
                    int bb = rr >> 8;
                    int tt = rr & 255;
                    g_ctrlT[(tt * HH + ng) * BATCH + bb] = v;
                }
            }
        }
    }
}

// ---------------------------------------------------------------------------
// Persistent decoder — dataflow version.
// 132 blocks x 512 thr. Block = (nt = bid>>1, mh = bid&1): 16 n x 32 m.
// 16 warps = 16 k-split groups. Thread: 1 m, 16 n (8 f32x2 accs).
// Cross-step activation loads via __ldcg (L2-coherent).
// ---------------------------------------------------------------------------
#define DEC_SMEM ((KD1*16 + DM*16 + 16*16*32) * 4)

__device__ __forceinline__ void dec_seg(
    u64 acc[8], const float* __restrict__ src, const float* __restrict__ Ws,
    int k0, int nk, int moff)
{
    const float* s = src + moff;
    const ulonglong2* wp = (const ulonglong2*)(Ws + k0 * 16);
    float av[4];
#pragma unroll
    for (int kk = 0; kk < 4; kk++) av[kk] = __ldcg(s + 64 * kk);

    for (int i = 0; i < nk; i += 4) {
        s += 256;
        float nv[4];
#pragma unroll
        for (int kk = 0; kk < 4; kk++) nv[kk] = __ldcg(s + 64 * kk);  // padded
#pragma unroll
        for (int kk = 0; kk < 4; kk++) {
            u64 ad = pk2(av[kk], av[kk]);
            ulonglong2 w0 = wp[0], w1 = wp[1], w2 = wp[2], w3 = wp[3];
            wp += 4;
            fma2(acc[0], ad, w0.x); fma2(acc[1], ad, w0.y);
            fma2(acc[2], ad, w1.x); fma2(acc[3], ad, w1.y);
            fma2(acc[4], ad, w2.x); fma2(acc[5], ad, w2.y);
            fma2(acc[6], ad, w3.x); fma2(acc[7], ad, w3.y);
        }
#pragma unroll
        for (int kk = 0; kk < 4; kk++) av[kk] = nv[kk];
    }
}

__global__ __launch_bounds__(512) void dec_persistent_kernel(
    const float* __restrict__ Wd1, const float* __restrict__ bd1,
    const float* __restrict__ Wd2, const float* __restrict__ bd2)
{
    extern __shared__ float sm[];
    float* Ws1 = sm;                        // [KD1][16]
    float* Ws2 = sm + KD1 * 16;             // [DM][16]
    float* red = sm + (KD1 + DM) * 16;      // [16g][16n][32m]

    int tid = threadIdx.x;
    int bid = blockIdx.x;
    int nt  = bid >> 1;          // n-tile 0..65
    int mh  = bid & 1;           // batch half
    int n0  = nt * 16;

    // replay-safe epoch base: own flag1 (only this block writes it)
    unsigned base = ld_rlx(&g_flag1[(nt * 2 + mh) * 32]);

    // one-time: cache weight slices k-row-major [k][16]
    for (int i = tid; i < 16 * KD1; i += 512) {
        int k = i >> 4, n = i & 15;
        Ws1[i] = Wd1[(size_t)k * DM + n0 + n];
    }
    if (nt < 64) {
        for (int i = tid; i < 16 * DM; i += 512) {
            int k = i >> 4, n = i & 15;
            Ws2[i] = Wd2[(size_t)k * SS + n0 + n];
        }
    }
    __syncthreads();

    int g    = tid >> 5;
    int lane = tid & 31;
    int moff = mh * 32 + lane;
    int en   = tid >> 5;
    int em   = tid & 31;

    float bv1 = bd1[n0 + en];
    float bv2 = (nt < 64) ? bd2[n0 + en] : 0.f;

    // k segments
    int kb1 = g * 68;                                    // 16 x 68 = 1088
    int kb2 = (g < 8) ? g * 68 : 544 + (g - 8) * 64;     // 8x68 + 8x64 = 1056
    int nk2 = (g < 8) ? 68 : 64;

    // producer tile ranges this warp depends on
    int p0 = (g == 0) ? 0 : (kb1 - HH) >> 4;             // flag2 tiles (prev out)
    int p1 = (g == 0) ? 0 : (kb1 + 3) >> 4;
    int q0 = kb2 >> 4;                                   // flag1 tiles (hdT)
    int q1 = (kb2 + nk2 - 1) >> 4;

    for (int t = 0; t < TT; t++) {
        const float* prevT = (t == 0) ? g_zero
                                      : g_outT + (size_t)(t - 1) * SS * BATCH;
        const float* ctrl_base = g_ctrlT + t * HH * BATCH;

        // ---- layer 1: g_hdT = relu([ctrl_t | prev] @ Wd1 + bd1), K=1088
        {
            u64 acc[8] = {};
            if (g == 0) {
                dec_seg(acc, ctrl_base, Ws1, 0, 64, moff);   // no dependency
                if (t > 0) wait_tiles(g_flag2, mh, 0, 0, base + t);
                dec_seg(acc, prevT, Ws1, 64, 4, moff);
            } else {
                if (t > 0) wait_tiles(g_flag2, mh, p0, p1, base + t);
                dec_seg(acc, prevT + (kb1 - HH) * 64, Ws1, kb1, 68, moff);
            }
#pragma unroll
            for (int p = 0; p < 8; p++) {
                float lo, hi; unpk2(acc[p], lo, hi);
                red[(g * 16 + 2 * p) * 32 + lane]     = lo;
                red[(g * 16 + 2 * p + 1) * 32 + lane] = hi;
            }
            __syncthreads();

            float v = bv1;
#pragma unroll
            for (int gg = 0; gg < 16; gg++)
                v += red[(gg * 16 + en) * 32 + em];
            g_hdT[(n0 + en) * 64 + mh * 32 + em] = fmaxf(v, 0.f);

            __threadfence();
            __syncthreads();
            if (tid == 0)
                st_rel(&g_flag1[(nt * 2 + mh) * 32], base + t + 1);
        }

        // ---- layer 2: out_t = g_hd @ Wd2 + bd2, K=1056
        if (nt < 64) {
            u64 acc[8] = {};
            wait_tiles(g_flag1, mh, q0, q1, base + t + 1);
            dec_seg(acc, g_hdT + kb2 * 64, Ws2, kb2, nk2, moff);
#pragma unroll
            for (int p = 0; p < 8; p++) {
                float lo, hi; unpk2(acc[p], lo, hi);
                red[(g * 16 + 2 * p) * 32 + lane]     = lo;
                red[(g * 16 + 2 * p + 1) * 32 + lane] = hi;
            }
            __syncthreads();

            float v = bv2;
#pragma unroll
            for (int gg = 0; gg < 16; gg++)
                v += red[(gg * 16 + en) * 32 + em];
            int s = n0 + en;
            g_outT[(size_t)t * SS * BATCH + s * BATCH + mh * 32 + em] = v;

            __threadfence();
            __syncthreads();
            if (tid == 0)
                st_rel(&g_flag2[(nt * 2 + mh) * 32], base + t + 1);
        }
    }
}

// ---------------------------------------------------------------------------
extern "C" void kernel_launch(void* const* d_in, const int* in_sizes, int n_in,
                              void* d_out, int out_size)
{
    const float* x   = (const float*)d_in[0];
    const float* We1 = (const float*)d_in[1];
    const float* be1 = (const float*)d_in[2];
    const float* We2 = (const float*)d_in[3];
    const float* be2 = (const float*)d_in[4];
    const float* Wd1 = (const float*)d_in[5];
    const float* bd1 = (const float*)d_in[6];
    const float* Wd2 = (const float*)d_in[7];
    const float* bd2 = (const float*)d_in[8];
    float* out = (float*)d_out;

    cudaFuncSetAttribute(dec_persistent_kernel,
                         cudaFuncAttributeMaxDynamicSharedMemorySize, DEC_SMEM);

    // encoder (parallel)
    transpose_x_kernel<<<dim3(TT / 32, SS / 32, BATCH), dim3(32, 8)>>>(x);
    enc_gemm_kernel<0><<<dim3((EM + 63) / 64, MROWS / 64), 256>>>(We1, be1);
    enc_gemm_kernel<1><<<dim3(1, MROWS / 64), 256>>>(We2, be2);

    // decoder: persistent dataflow kernel over all 256 steps
    dec_persistent_kernel<<<NBLK, 512, DEC_SMEM>>>(Wd1, bd1, Wd2, bd2);

    // final layout fix: g_outT[t,s,b] -> out[b,s,t]
    transpose_out_kernel<<<dim3(TT / 32, BATCH / 32, SS), dim3(32, 8)>>>(out);
}

// round 11
// speedup vs baseline: 1.1819x; 1.0696x over previous
#include <cuda_runtime.h>

// ---------------------------------------------------------------------------
// StepWiseMLPAutoEncoder — fp32, packed fma.rn.f32x2
// R4 decoder (measured best) + NEW 128x128-tile encoder layer-1 GEMM
// ---------------------------------------------------------------------------

#define BATCH 64
#define SS    1024
#define TT    256
#define HH    64
#define EM    1056
#define DM    1056
#define KC    2048
#define KD1   1088
#define MROWS (BATCH*TT)
#define NBLK  132

typedef unsigned long long u64;

// scratch (device globals) — padded +256 floats for prefetch overshoot
__device__ float g_xT[BATCH * TT * SS];
__device__ float g_h1[(size_t)MROWS * EM];
__device__ float g_ctrlT[TT * HH * BATCH + 256];     // [T,H,B] k-major
__device__ float g_hdT[DM * BATCH + 256];            // [K,B]
__device__ float g_sbufT[2][SS * BATCH + 256];       // [S,B] ping-pong
__device__ unsigned g_bar = 0;
__device__ unsigned g_gen = 0;

// ---- packed fp32x2 helpers -------------------------------------------------
__device__ __forceinline__ u64 pk2(float lo, float hi) {
    u64 r; asm("mov.b64 %0, {%1, %2};" : "=l"(r) : "f"(lo), "f"(hi)); return r;
}
__device__ __forceinline__ void fma2(u64& d, u64 a, u64 b) {
    asm("fma.rn.f32x2 %0, %1, %2, %0;" : "+l"(d) : "l"(a), "l"(b));
}
__device__ __forceinline__ void unpk2(u64 v, float& lo, float& hi) {
    asm("mov.b64 {%0, %1}, %2;" : "=f"(lo), "=f"(hi) : "l"(v));
}

// ---------------------------------------------------------------------------
__device__ __forceinline__ void grid_sync(int nb)
{
    __threadfence();
    __syncthreads();
    if (threadIdx.x == 0) {
        volatile unsigned* vgen = &g_gen;
        unsigned my = *vgen;
        if (atomicAdd(&g_bar, 1u) == (unsigned)(nb - 1)) {
            atomicExch(&g_bar, 0u);
            __threadfence();
            atomicExch(&g_gen, my + 1u);
        } else {
            while (*vgen == my) { }
            __threadfence();
        }
    }
    __syncthreads();
}

// ---------------------------------------------------------------------------
// x[b,s,t] -> xT[b,t,s]
// ---------------------------------------------------------------------------
__global__ void transpose_x_kernel(const float* __restrict__ x)
{
    __shared__ float tile[32][33];
    int b  = blockIdx.z;
    int t0 = blockIdx.x * 32;
    int s0 = blockIdx.y * 32;
    const float* xb  = x    + (size_t)b * SS * TT;
    float*       xTb = g_xT + (size_t)b * TT * SS;
    int tx = threadIdx.x, ty = threadIdx.y;
#pragma unroll
    for (int j = 0; j < 32; j += 8)
        tile[ty + j][tx] = xb[(s0 + ty + j) * TT + t0 + tx];
    __syncthreads();
#pragma unroll
    for (int j = 0; j < 32; j += 8)
        xTb[(t0 + ty + j) * SS + s0 + tx] = tile[tx][ty + j];
}

// ---------------------------------------------------------------------------
// NEW enc0: h1 = relu(comb @ We1 + be1). 128x128 tile, BK=16, 256 threads,
// 8m x 8n per thread (32 f32x2 accumulators), register-staged smem fill.
// grid = (ceil(EM/128)=9, MROWS/128=128)
// ---------------------------------------------------------------------------
__global__ __launch_bounds__(256, 2) void enc0_kernel(
    const float* __restrict__ We1, const float* __restrict__ be1)
{
    __shared__ float As[16][132];   // [k][m], padded (16B-aligned rows)
    __shared__ float Bs[16][128];   // [k][n]

    int tid = threadIdx.x;
    int n0  = blockIdx.x * 128;
    int r0  = blockIdx.y * 128;
    int tm  = tid >> 4;             // 0..15 -> rows tm*8..
    int tn  = tid & 15;             // 0..15 -> cols tn*8..

    // loader geometry: 512 float4 per tile, 2 per thread (it = 0,1)
    // A: row = f>>2, kcol = (f&3)*4 ;  B: k = f>>5, n4 = (f&31)*4
    int arow[2], acol[2];
    const float* acur[2];
    const float* aprev[2];
#pragma unroll
    for (int it = 0; it < 2; it++) {
        int f = tid + it * 256;
        arow[it] = f >> 2;
        acol[it] = (f & 3) * 4;
        int r = r0 + arow[it];
        int b = r >> 8, t = r & 255;
        acur[it]  = g_xT + ((size_t)(b << 8) + t) * SS;
        aprev[it] = (t > 0) ? (acur[it] - SS) : nullptr;
    }
    int bk[2], bn[2];
#pragma unroll
    for (int it = 0; it < 2; it++) {
        int f = tid + it * 256;
        bk[it] = f >> 5;
        bn[it] = (f & 31) * 4;
    }

    u64 acc[8][4];
#pragma unroll
    for (int i = 0; i < 8; i++)
#pragma unroll
        for (int j = 0; j < 4; j++) acc[i][j] = 0ULL;

    float4 a_s[2], b_s[2];
    // preload chunk 0
#pragma unroll
    for (int it = 0; it < 2; it++) {
        int kg = acol[it];
        float4 v = make_float4(0.f, 0.f, 0.f, 0.f);
        if (kg < SS) { if (aprev[it]) v = *(const float4*)(aprev[it] + kg); }
        else           v = *(const float4*)(acur[it] + kg - SS);
        a_s[it] = v;
        int ng = n0 + bn[it];
        float4 w = make_float4(0.f, 0.f, 0.f, 0.f);
        if (ng < EM) w = *(const float4*)&We1[(size_t)bk[it] * EM + ng];
        b_s[it] = w;
    }

    for (int kc = 0; kc < KC; kc += 16) {
        __syncthreads();   // previous compute done (no-op first iter)
#pragma unroll
        for (int it = 0; it < 2; it++) {
            As[acol[it] + 0][arow[it]] = a_s[it].x;
            As[acol[it] + 1][arow[it]] = a_s[it].y;
            As[acol[it] + 2][arow[it]] = a_s[it].z;
            As[acol[it] + 3][arow[it]] = a_s[it].w;
            *(float4*)&Bs[bk[it]][bn[it]] = b_s[it];
        }
        __syncthreads();

        if (kc + 16 < KC) {
#pragma unroll
            for (int it = 0; it < 2; it++) {
                int kg = kc + 16 + acol[it];
                float4 v = make_float4(0.f, 0.f, 0.f, 0.f);
                if (kg < SS) { if (aprev[it]) v = *(const float4*)(aprev[it] + kg); }
                else           v = *(const float4*)(acur[it] + kg - SS);
                a_s[it] = v;
                int ng = n0 + bn[it];
                float4 w = make_float4(0.f, 0.f, 0.f, 0.f);
                if (ng < EM) w = *(const float4*)&We1[(size_t)(kc + 16 + bk[it]) * EM + ng];
                b_s[it] = w;
            }
        }

#pragma unroll
        for (int kk = 0; kk < 16; kk++) {
            float4 a0 = *(const float4*)&As[kk][tm * 8];
            float4 a1 = *(const float4*)&As[kk][tm * 8 + 4];
            ulonglong2 w0 = *(const ulonglong2*)&Bs[kk][tn * 8];
            ulonglong2 w1 = *(const ulonglong2*)&Bs[kk][tn * 8 + 4];
            float am[8] = {a0.x, a0.y, a0.z, a0.w, a1.x, a1.y, a1.z, a1.w};
#pragma unroll
            for (int i = 0; i < 8; i++) {
                u64 ad = pk2(am[i], am[i]);
                fma2(acc[i][0], ad, w0.x);
                fma2(acc[i][1], ad, w0.y);
                fma2(acc[i][2], ad, w1.x);
                fma2(acc[i][3], ad, w1.y);
            }
        }
    }

    // epilogue
#pragma unroll
    for (int i = 0; i < 8; i++) {
        float c[8];
        unpk2(acc[i][0], c[0], c[1]);
        unpk2(acc[i][1], c[2], c[3]);
        unpk2(acc[i][2], c[4], c[5]);
        unpk2(acc[i][3], c[6], c[7]);
        int rr = r0 + tm * 8 + i;
        float* dst = g_h1 + (size_t)rr * EM;
#pragma unroll
        for (int j = 0; j < 8; j++) {
            int ng = n0 + tn * 8 + j;
            if (ng < EM) dst[ng] = fmaxf(c[j] + be1[ng], 0.f);
        }
    }
}

// ---------------------------------------------------------------------------
// Encoder layer-2 GEMM (unchanged R4): 64x64 tile, 256 threads.
// A = g_h1, C = A@We2+be2 -> g_ctrlT
// ---------------------------------------------------------------------------
__global__ __launch_bounds__(256) void enc1_kernel(
    const float* __restrict__ Bmat, const float* __restrict__ bias)
{
    constexpr int N = HH;
    constexpr int K = EM;

    __shared__ float As[16][64];
    __shared__ float Bs[16][64];

    int tid  = threadIdx.x;
    int arow = tid >> 2;
    int acol = (tid & 3) * 4;
    int tn   = tid & 15;
    int tm   = tid >> 4;
    int r0   = blockIdx.y * 64;

    u64 acc2[4][2];
#pragma unroll
    for (int i = 0; i < 4; i++) { acc2[i][0] = 0ULL; acc2[i][1] = 0ULL; }

    const float* acur = g_h1 + (size_t)(r0 + arow) * K;

    for (int kc = 0; kc < K; kc += 16) {
        float4 av = *(const float4*)(acur + kc + acol);
        As[acol + 0][arow] = av.x;
        As[acol + 1][arow] = av.y;
        As[acol + 2][arow] = av.z;
        As[acol + 3][arow] = av.w;

#pragma unroll
        for (int it = 0; it < 4; it++) {
            int k = (tid >> 6) + it * 4;
            int n = tid & 63;
            float v = 0.f;
            if (n < N) v = Bmat[(size_t)(kc + k) * N + n];
            Bs[k][n] = v;
        }
        __syncthreads();

#pragma unroll
        for (int kk = 0; kk < 16; kk++) {
            float4 a4 = *(const float4*)&As[kk][tm * 4];
            ulonglong2 b2 = *(const ulonglong2*)&Bs[kk][tn * 4];
            u64 d0 = pk2(a4.x, a4.x);
            u64 d1 = pk2(a4.y, a4.y);
            u64 d2 = pk2(a4.z, a4.z);
            u64 d3 = pk2(a4.w, a4.w);
            fma2(acc2[0][0], d0, b2.x); fma2(acc2[0][1], d0, b2.y);
            fma2(acc2[1][0], d1, b2.x); fma2(acc2[1][1], d1, b2.y);
            fma2(acc2[2][0], d2, b2.x); fma2(acc2[2][1], d2, b2.y);
            fma2(acc2[3][0], d3, b2.x); fma2(acc2[3][1], d3, b2.y);
        }
        __syncthreads();
    }

#pragma unroll
    for (int i = 0; i < 4; i++) {
        float c[4];
        unpk2(acc2[i][0], c[0], c[1]);
        unpk2(acc2[i][1], c[2], c[3]);
        int rr = r0 + tm * 4 + i;
#pragma unroll
        for (int j = 0; j < 4; j++) {
            int ng = tn * 4 + j;
            if (ng < N) {
                float v = c[j] + bias[ng];
                int bb = rr >> 8;
                int tt = rr & 255;
                g_ctrlT[(tt * HH + ng) * BATCH + bb] = v;
            }
        }
    }
}

// ---------------------------------------------------------------------------
// Persistent decoder — R4 verbatim (measured best).
// 132 blocks x 512 thr. Block = (nt = bid>>1, mh = bid&1): 16 n x 32 m.
// 16 warps = 16 k-split groups. Thread: 1 m, 16 n (8 f32x2 accs).
// ---------------------------------------------------------------------------
#define DEC_SMEM ((KD1*16 + DM*16 + 16*16*32) * 4)

__device__ __forceinline__ void dec_seg(
    u64 acc[8], const float* __restrict__ src, const float* __restrict__ Ws,
    int k0, int nk, int moff)
{
    const float* s = src + moff;
    const ulonglong2* wp = (const ulonglong2*)(Ws + k0 * 16);
    float av[4];
#pragma unroll
    for (int kk = 0; kk < 4; kk++) av[kk] = s[64 * kk];

    for (int i = 0; i < nk; i += 4) {
        s += 256;
        float nv[4];
#pragma unroll
        for (int kk = 0; kk < 4; kk++) nv[kk] = s[64 * kk];  // prefetch (padded)
#pragma unroll
        for (int kk = 0; kk < 4; kk++) {
            u64 ad = pk2(av[kk], av[kk]);
            ulonglong2 w0 = wp[0], w1 = wp[1], w2 = wp[2], w3 = wp[3];
            wp += 4;
            fma2(acc[0], ad, w0.x); fma2(acc[1], ad, w0.y);
            fma2(acc[2], ad, w1.x); fma2(acc[3], ad, w1.y);
            fma2(acc[4], ad, w2.x); fma2(acc[5], ad, w2.y);
            fma2(acc[6], ad, w3.x); fma2(acc[7], ad, w3.y);
        }
#pragma unroll
        for (int kk = 0; kk < 4; kk++) av[kk] = nv[kk];
    }
}

__global__ __launch_bounds__(512) void dec_persistent_kernel(
    const float* __restrict__ Wd1, const float* __restrict__ bd1,
    const float* __restrict__ Wd2, const float* __restrict__ bd2,
    float* __restrict__ out)
{
    extern __shared__ float sm[];
    float* Ws1 = sm;                        // [KD1][16]
    float* Ws2 = sm + KD1 * 16;             // [DM][16]
    float* red = sm + (KD1 + DM) * 16;      // [16g][16n][32m]

    int tid = threadIdx.x;
    int bid = blockIdx.x;
    int nt  = bid >> 1;          // n-tile 0..65
    int mh  = bid & 1;           // m-half
    int n0  = nt * 16;

    for (int i = tid; i < 16 * KD1; i += 512) {
        int k = i >> 4, n = i & 15;
        Ws1[i] = Wd1[(size_t)k * DM + n0 + n];
    }
    if (nt < 64) {
        for (int i = tid; i < 16 * DM; i += 512) {
            int k = i >> 4, n = i & 15;
            Ws2[i] = Wd2[(size_t)k * SS + n0 + n];
        }
    }
    {
        int i = bid * 512 + tid;
        if (i < SS * BATCH) g_sbufT[0][i] = 0.f;
        if (i < 256) { g_sbufT[0][SS * BATCH + i] = 0.f; g_sbufT[1][SS * BATCH + i] = 0.f; }
    }

    int g    = tid >> 5;             // k-split group = warp 0..15
    int lane = tid & 31;
    int moff = mh * 32 + lane;       // global batch row
    int en   = tid >> 5;             // epilogue n 0..15
    int em   = tid & 31;             // epilogue m 0..31

    float bv1 = bd1[n0 + en];
    float bv2 = (nt < 64) ? bd2[n0 + en] : 0.f;

    grid_sync(NBLK);

    for (int t = 0; t < TT; t++) {
        const float* sbT = g_sbufT[t & 1];
        const float* ctrl_base = g_ctrlT + t * HH * BATCH;

        // ---- layer 1: g_hdT = relu([ctrl_t | prev] @ Wd1 + bd1), K=1088
        {
            u64 acc[8] = {};
            if (g == 0) {
                dec_seg(acc, ctrl_base, Ws1, 0, 64, moff);      // k 0..63
                dec_seg(acc, sbT, Ws1, 64, 4, moff);            // k 64..67
            } else {
                int kb = g * 68;                                 // 16*68 = 1088
                dec_seg(acc, sbT + (kb - HH) * 64, Ws1, kb, 68, moff);
            }
#pragma unroll
            for (int p = 0; p < 8; p++) {
                float lo, hi; unpk2(acc[p], lo, hi);
                red[(g * 16 + 2 * p) * 32 + lane]     = lo;
                red[(g * 16 + 2 * p + 1) * 32 + lane] = hi;
            }
            __syncthreads();

            float v = bv1;
#pragma unroll
            for (int gg = 0; gg < 16; gg++)
                v += red[(gg * 16 + en) * 32 + em];
            g_hdT[(n0 + en) * 64 + mh * 32 + em] = fmaxf(v, 0.f);
        }
        grid_sync(NBLK);

        // ---- layer 2: out_t = g_hd @ Wd2 + bd2, K=1056
        if (nt < 64) {
            u64 acc[8] = {};
            int kb  = (g < 8) ? g * 68 : 544 + (g - 8) * 64;    // 8*68+8*64 = 1056
            int nk2 = (g < 8) ? 68 : 64;
            dec_seg(acc, g_hdT + kb * 64, Ws2, kb, nk2, moff);
#pragma unroll
            for (int p = 0; p < 8; p++) {
                float lo, hi; unpk2(acc[p], lo, hi);
                red[(g * 16 + 2 * p) * 32 + lane]     = lo;
                red[(g * 16 + 2 * p + 1) * 32 + lane] = hi;
            }
            __syncthreads();

            float v = bv2;
#pragma unroll
            for (int gg = 0; gg < 16; gg++)
                v += red[(gg * 16 + en) * 32 + em];
            int s = n0 + en;
            int m = mh * 32 + em;
            g_sbufT[(t + 1) & 1][s * 64 + m] = v;
            out[((size_t)m * SS + s) * TT + t] = v;
        }
        grid_sync(NBLK);
    }
}

// ---------------------------------------------------------------------------
extern "C" void kernel_launch(void* const* d_in, const int* in_sizes, int n_in,
                              void* d_out, int out_size)
{
    const float* x   = (const float*)d_in[0];
    const float* We1 = (const float*)d_in[1];
    const float* be1 = (const float*)d_in[2];
    const float* We2 = (const float*)d_in[3];
    const float* be2 = (const float*)d_in[4];
    const float* Wd1 = (const float*)d_in[5];
    const float* bd1 = (const float*)d_in[6];
    const float* Wd2 = (const float*)d_in[7];
    const float* bd2 = (const float*)d_in[8];
    float* out = (float*)d_out;

    cudaFuncSetAttribute(dec_persistent_kernel,
                         cudaFuncAttributeMaxDynamicSharedMemorySize, DEC_SMEM);

    transpose_x_kernel<<<dim3(TT / 32, SS / 32, BATCH), dim3(32, 8)>>>(x);
    enc0_kernel<<<dim3((EM + 127) / 128, MROWS / 128), 256>>>(We1, be1);
    enc1_kernel<<<dim3(1, MROWS / 64), 256>>>(We2, be2);

    dec_persistent_kernel<<<NBLK, 512, DEC_SMEM>>>(Wd1, bd1, Wd2, bd2, out);
}